// round 6
// baseline (speedup 1.0000x reference)
#include <cuda_runtime.h>
#include <cstdint>

typedef unsigned long long ull;

// ---------- packed f32x2 helpers ----------
__device__ __forceinline__ ull f2pack(float lo, float hi) {
    ull r; asm("mov.b64 %0,{%1,%2};" : "=l"(r) : "f"(lo), "f"(hi)); return r;
}
__device__ __forceinline__ void f2unpack(ull a, float& lo, float& hi) {
    asm("mov.b64 {%0,%1},%2;" : "=f"(lo), "=f"(hi) : "l"(a));
}
__device__ __forceinline__ ull f2mul(ull a, ull b) {
    ull r; asm("mul.rn.f32x2 %0,%1,%2;" : "=l"(r) : "l"(a), "l"(b)); return r;
}
__device__ __forceinline__ ull f2add(ull a, ull b) {
    ull r; asm("add.rn.f32x2 %0,%1,%2;" : "=l"(r) : "l"(a), "l"(b)); return r;
}
__device__ __forceinline__ ull f2fma(ull a, ull b, ull c) {
    ull r; asm("fma.rn.f32x2 %0,%1,%2,%3;" : "=l"(r) : "l"(a), "l"(b), "l"(c)); return r;
}

#define TILE_W    32
#define TILE_H    22
#define HALO      5
#define IN_ROWS   32                   // TILE_H + 10 == one full warp of rows
#define IN_W      42                   // TILE_W + 10
#define SPT_CPITCH 43                  // cells per row; row stride = 86 ull (172 words) -> CF LDS.128
#define SPT_RSTRIDE (2 * SPT_CPITCH)   // 86 ull
#define SPT_SIZE  (IN_ROWS * SPT_RSTRIDE)  // 2752 ull
#define HB_RSTRIDE 66                  // 2 ull cells * 33 pitch; 132 words -> CF STS/LDS.128
#define HB_SIZE   (IN_ROWS * HB_RSTRIDE)   // 2112 ull per pair-plane
#define NPIX      12582912.0           // 48 * 512 * 512
#define NBLOCKS   9216                 // 16 x 24 x 24

__device__ double        g_acc  = 0.0;
__device__ unsigned int  g_done = 0u;

// ---- vertical 2-pass (2 signals each), NO outputs at row y0; stage in dead spt smem ----
template<int NO>
__device__ __forceinline__ float v_phase(ull* __restrict__ sm,
                                         const ull* __restrict__ hb01,
                                         const ull* __restrict__ hb23,
                                         const ull ww[11], int lane, int y0, int gy0)
{
    const ull TWO  = f2pack(2.0f, 2.0f);
    const ull C1p  = f2pack(1e-4f, 1e-4f);
    const ull C2p  = f2pack(9e-4f, 9e-4f);
    const ull C12p = f2pack(1e-4f + 9e-4f, 1e-4f + 9e-4f);
    const ull EPSp = f2pack(1e-8f, 1e-8f);
    const ull SGN  = 0x8000000080000000ULL;

    // ---- pass A: mu1, mu2 -> stage {m12, den1} ----
    {
        ull a0[NO], a1[NO];
#pragma unroll
        for (int j = 0; j < NO; j++) { a0[j] = 0ULL; a1[j] = 0ULL; }
        const ull* b = hb01 + y0 * HB_RSTRIDE + 2 * lane;
#pragma unroll
        for (int k = 0; k < NO + 10; k++) {
            ulonglong2 v = *reinterpret_cast<const ulonglong2*>(b + k * HB_RSTRIDE);
#pragma unroll
            for (int j = 0; j < NO; j++) {
                const int ki = k - j;
                if (ki >= 0 && ki <= 10) {
                    ull w = ww[ki];
                    a0[j] = f2fma(v.x, w, a0[j]);
                    a1[j] = f2fma(v.y, w, a1[j]);
                }
            }
        }
#pragma unroll
        for (int j = 0; j < NO; j++) {
            ull mu1 = a0[j], mu2 = a1[j];
            ull m12  = f2mul(mu1, mu2);
            ull den1 = f2fma(mu1, mu1, f2fma(mu2, mu2, C1p));     // mu1^2+mu2^2+C1
            ull* stg = sm + ((y0 + j) * 32 + lane) * 2;
            *reinterpret_cast<ulonglong2*>(stg) = make_ulonglong2(m12, den1);
        }
    }

    // ---- pass B: sq, pt -> epilogue ----
    float lsum = 0.f;
    {
        ull a2[NO], a3[NO];
#pragma unroll
        for (int j = 0; j < NO; j++) { a2[j] = 0ULL; a3[j] = 0ULL; }
        const ull* b = hb23 + y0 * HB_RSTRIDE + 2 * lane;
#pragma unroll
        for (int k = 0; k < NO + 10; k++) {
            ulonglong2 v = *reinterpret_cast<const ulonglong2*>(b + k * HB_RSTRIDE);
#pragma unroll
            for (int j = 0; j < NO; j++) {
                const int ki = k - j;
                if (ki >= 0 && ki <= 10) {
                    ull w = ww[ki];
                    a2[j] = f2fma(v.x, w, a2[j]);
                    a3[j] = f2fma(v.y, w, a3[j]);
                }
            }
        }
#pragma unroll
        for (int j = 0; j < NO; j++) {
            if (gy0 + j < 512) {
                const ull* stg = sm + ((y0 + j) * 32 + lane) * 2;
                ulonglong2 md = *reinterpret_cast<const ulonglong2*>(stg);
                ull m12 = md.x, den1 = md.y;
                ull den2  = f2add(f2add(a2[j], C12p), den1 ^ SGN);  // bsq - den1 + C1+C2
                ull sig12 = f2add(a3[j], m12 ^ SGN);                // bpt - m12
                ull num1  = f2fma(m12,   TWO, C1p);
                ull num2  = f2fma(sig12, TWO, C2p);
                ull num   = f2mul(num1, num2);
                ull den   = f2fma(den1, den2, EPSp);
                float n0, n1, d0, d1;
                f2unpack(num, n0, n1);
                f2unpack(den, d0, d1);
                lsum += __fdividef(n0, d0) + __fdividef(n1, d1);
            }
        }
    }
    return lsum;
}

// smem (ull): spt[2752] | hb01[2112] | hb23[2112] -> 6976 ull = 55808 B; 4 CTAs/SM
__global__ __launch_bounds__(256, 4) void ssim_main_k(
    const float* __restrict__ pred,
    const float* __restrict__ targ,
    const float* __restrict__ win,
    float* __restrict__ out)
{
    extern __shared__ ull sm[];
    ull* spt  = sm;
    ull* hb01 = sm + SPT_SIZE;
    ull* hb23 = sm + SPT_SIZE + HB_SIZE;

    const int tid  = threadIdx.x;
    const int lane = tid & 31;
    const int warp = tid >> 5;

    // --- recover separable 1D window: w1[j] = win[55+j] / sum_j win[55+j] ---
    float rowsum = 0.f;
#pragma unroll
    for (int j = 0; j < 11; j++) rowsum += __ldg(win + 55 + j);
    const float invr = 1.0f / rowsum;
    ull ww[11];
#pragma unroll
    for (int j = 0; j < 11; j++) {
        float w = __ldg(win + 55 + j) * invr;
        ww[j] = f2pack(w, w);
    }

    const int ox = blockIdx.x * TILE_W;
    const int oy = blockIdx.y * TILE_H;
    const int pz = blockIdx.z;                  // plane pair 0..23
    const float* p0 = pred + (size_t)pz * 524288;
    const float* p1 = p0 + 262144;
    const float* t0 = targ + (size_t)pz * 524288;
    const float* t1 = t0 + 262144;

    // --- load 32x42 halo tile (zero pad) into interleaved {p,t} cells ---
#pragma unroll
    for (int i = 0; i < 6; i++) {
        int idx = tid + i * 256;
        if (idx < IN_ROWS * IN_W) {
            int r = idx / IN_W, c = idx - r * IN_W;
            int gy = oy + r - HALO, gx = ox + c - HALO;
            bool inb = ((unsigned)gy < 512u) && ((unsigned)gx < 512u);
            float a0 = 0.f, a1 = 0.f, b0 = 0.f, b1 = 0.f;
            if (inb) {
                int g = gy * 512 + gx;
                a0 = __ldg(p0 + g); a1 = __ldg(p1 + g);
                b0 = __ldg(t0 + g); b1 = __ldg(t1 + g);
            }
            ull* cell = spt + r * SPT_RSTRIDE + 2 * c;
            *reinterpret_cast<ulonglong2*>(cell) =
                make_ulonglong2(f2pack(a0, a1), f2pack(b0, b1));
        }
    }
    __syncthreads();

    // --- horizontal blur: lane = row (32 exactly), warp = 4-wide x-group ---
    {
        const int r  = lane;
        const int x0 = warp * 4;
        const ull* rowp = spt + r * SPT_RSTRIDE + 2 * x0;
        ull am1[4], am2[4], asq[4], apt[4];
#pragma unroll
        for (int j = 0; j < 4; j++) { am1[j] = 0ULL; am2[j] = 0ULL; asq[j] = 0ULL; apt[j] = 0ULL; }
#pragma unroll
        for (int k = 0; k < 14; k++) {
            ulonglong2 PT = *reinterpret_cast<const ulonglong2*>(rowp + 2 * k);
            ull p = PT.x, t = PT.y;
            ull sq = f2fma(p, p, f2mul(t, t));   // p^2 + t^2
            ull pt = f2mul(p, t);
#pragma unroll
            for (int j = 0; j < 4; j++) {
                const int ki = k - j;
                if (ki >= 0 && ki <= 10) {
                    ull w = ww[ki];
                    am1[j] = f2fma(p,  w, am1[j]);
                    am2[j] = f2fma(t,  w, am2[j]);
                    asq[j] = f2fma(sq, w, asq[j]);
                    apt[j] = f2fma(pt, w, apt[j]);
                }
            }
        }
#pragma unroll
        for (int j = 0; j < 4; j++) {
            ull* c01 = hb01 + r * HB_RSTRIDE + 2 * (x0 + j);
            ull* c23 = hb23 + r * HB_RSTRIDE + 2 * (x0 + j);
            *reinterpret_cast<ulonglong2*>(c01) = make_ulonglong2(am1[j], am2[j]);
            *reinterpret_cast<ulonglong2*>(c23) = make_ulonglong2(asq[j], apt[j]);
        }
    }
    __syncthreads();

    // --- vertical blur + epilogue: 3 warps, NO = 8,8,6 (others idle -> reduction) ---
    float lsum = 0.f;
    if (warp == 0)      lsum = v_phase<8>(sm, hb01, hb23, ww, lane, 0,  oy);
    else if (warp == 1) lsum = v_phase<8>(sm, hb01, hb23, ww, lane, 8,  oy + 8);
    else if (warp == 2) lsum = v_phase<6>(sm, hb01, hb23, ww, lane, 16, oy + 16);

    // --- block reduction -> double atomic + last-block finalize ---
#pragma unroll
    for (int o = 16; o; o >>= 1) lsum += __shfl_xor_sync(0xffffffffu, lsum, o);
    __shared__ float warp_part[8];
    if (lane == 0) warp_part[warp] = lsum;
    __syncthreads();
    if (tid == 0) {
        float v = 0.f;
#pragma unroll
        for (int i = 0; i < 8; i++) v += warp_part[i];
        atomicAdd(&g_acc, (double)v);
        __threadfence();
        unsigned int old = atomicAdd(&g_done, 1u);
        if (old == NBLOCKS - 1u) {
            __threadfence();
            double total = *((volatile double*)&g_acc);
            out[0] = 1.0f - (float)(total * (1.0 / NPIX));
            g_acc  = 0.0;
            g_done = 0u;
        }
    }
}

extern "C" void kernel_launch(void* const* d_in, const int* in_sizes, int n_in,
                              void* d_out, int out_size)
{
    const float* pred = (const float*)d_in[0];
    const float* targ = (const float*)d_in[1];
    const float* win  = (const float*)d_in[2];
    float* out = (float*)d_out;

    const int smem_bytes = 55808;
    cudaFuncSetAttribute(ssim_main_k, cudaFuncAttributeMaxDynamicSharedMemorySize, smem_bytes);

    dim3 grid(16, 24, 24), blk(256);
    ssim_main_k<<<grid, blk, smem_bytes>>>(pred, targ, win, out);
}

// round 7
// speedup vs baseline: 1.1531x; 1.1531x over previous
#include <cuda_runtime.h>
#include <cstdint>

typedef unsigned long long ull;

// ---------- packed f32x2 helpers ----------
__device__ __forceinline__ ull f2pack(float lo, float hi) {
    ull r; asm("mov.b64 %0,{%1,%2};" : "=l"(r) : "f"(lo), "f"(hi)); return r;
}
__device__ __forceinline__ void f2unpack(ull a, float& lo, float& hi) {
    asm("mov.b64 {%0,%1},%2;" : "=f"(lo), "=f"(hi) : "l"(a));
}
__device__ __forceinline__ ull f2mul(ull a, ull b) {
    ull r; asm("mul.rn.f32x2 %0,%1,%2;" : "=l"(r) : "l"(a), "l"(b)); return r;
}
__device__ __forceinline__ ull f2add(ull a, ull b) {
    ull r; asm("add.rn.f32x2 %0,%1,%2;" : "=l"(r) : "l"(a), "l"(b)); return r;
}
__device__ __forceinline__ ull f2fma(ull a, ull b, ull c) {
    ull r; asm("fma.rn.f32x2 %0,%1,%2,%3;" : "=l"(r) : "l"(a), "l"(b), "l"(c)); return r;
}

#define TILE_W    32
#define TILE_H    22
#define HALO      5
#define IN_ROWS   32                       // TILE_H + 10 == one full warp of rows
#define IN_W      42                       // TILE_W + 10
#define SPT_RSTRIDE 86                     // 2 ull cells * 43 pitch; 172 words -> CF LDS.128
#define SPT_SIZE  (IN_ROWS * SPT_RSTRIDE)  // 2752 ull
#define HB_RSTRIDE 66                      // 2 ull cells * 33 pitch; 132 words -> CF STS/LDS.128
#define HB_SIZE   (IN_ROWS * HB_RSTRIDE)   // 2112 ull per pair-plane
#define NPIX      12582912.0               // 48 * 512 * 512
#define NBLOCKS   9216                     // 16 x 24 x 24

__device__ double        g_acc  = 0.0;
__device__ unsigned int  g_done = 0u;

// ---- vertical 2-pass (2 interleaved signals per pass), NO outputs at row y0 ----
template<int NO>
__device__ __forceinline__ float v_phase(const ull* __restrict__ hb01,
                                         const ull* __restrict__ hb23,
                                         const ull ww[11], int lane, int y0, int gy0)
{
    const ull TWO  = f2pack(2.0f, 2.0f);
    const ull C1p  = f2pack(1e-4f, 1e-4f);
    const ull C2p  = f2pack(9e-4f, 9e-4f);
    const ull C12p = f2pack(1e-4f + 9e-4f, 1e-4f + 9e-4f);
    const ull EPSp = f2pack(1e-8f, 1e-8f);
    const ull SGN  = 0x8000000080000000ULL;

    ull m12[NO], den1[NO];

    // ---- pass A: {mu1, mu2} ----
    {
        ull a0[NO], a1[NO];
#pragma unroll
        for (int j = 0; j < NO; j++) { a0[j] = 0ULL; a1[j] = 0ULL; }
        const ull* b = hb01 + y0 * HB_RSTRIDE + 2 * lane;
#pragma unroll
        for (int k = 0; k < NO + 10; k++) {
            ulonglong2 v = *reinterpret_cast<const ulonglong2*>(b + k * HB_RSTRIDE);
#pragma unroll
            for (int j = 0; j < NO; j++) {
                const int ki = k - j;
                if (ki >= 0 && ki <= 10) {
                    ull w = ww[ki];
                    a0[j] = f2fma(v.x, w, a0[j]);
                    a1[j] = f2fma(v.y, w, a1[j]);
                }
            }
        }
#pragma unroll
        for (int j = 0; j < NO; j++) {
            ull mu1 = a0[j], mu2 = a1[j];
            m12[j]  = f2mul(mu1, mu2);
            den1[j] = f2fma(mu1, mu1, f2fma(mu2, mu2, C1p));     // mu1^2+mu2^2+C1
        }
    }

    // ---- pass B: {sq, pt} -> epilogue ----
    float lsum = 0.f;
    {
        ull a2[NO], a3[NO];
#pragma unroll
        for (int j = 0; j < NO; j++) { a2[j] = 0ULL; a3[j] = 0ULL; }
        const ull* b = hb23 + y0 * HB_RSTRIDE + 2 * lane;
#pragma unroll
        for (int k = 0; k < NO + 10; k++) {
            ulonglong2 v = *reinterpret_cast<const ulonglong2*>(b + k * HB_RSTRIDE);
#pragma unroll
            for (int j = 0; j < NO; j++) {
                const int ki = k - j;
                if (ki >= 0 && ki <= 10) {
                    ull w = ww[ki];
                    a2[j] = f2fma(v.x, w, a2[j]);
                    a3[j] = f2fma(v.y, w, a3[j]);
                }
            }
        }
#pragma unroll
        for (int j = 0; j < NO; j++) {
            if (gy0 + j < 512) {
                ull den2  = f2add(f2add(a2[j], C12p), den1[j] ^ SGN);  // bsq - den1 + C1+C2
                ull sig12 = f2add(a3[j], m12[j] ^ SGN);                // bpt - m12
                ull num1  = f2fma(m12[j], TWO, C1p);
                ull num2  = f2fma(sig12,  TWO, C2p);
                ull num   = f2mul(num1, num2);
                ull den   = f2fma(den1[j], den2, EPSp);
                float n0, n1, d0, d1;
                f2unpack(num, n0, n1);
                f2unpack(den, d0, d1);
                lsum += __fdividef(n0, d0) + __fdividef(n1, d1);
            }
        }
    }
    return lsum;
}

// smem (ull): spt[2752] | hb01[2112] | hb23[2112] -> 6976 ull = 55808 B; 4 CTAs/SM
__global__ __launch_bounds__(256, 4) void ssim_main_k(
    const float* __restrict__ pred,
    const float* __restrict__ targ,
    const float* __restrict__ win,
    float* __restrict__ out)
{
    extern __shared__ ull sm[];
    ull* spt  = sm;
    ull* hb01 = sm + SPT_SIZE;
    ull* hb23 = sm + SPT_SIZE + HB_SIZE;

    const int tid  = threadIdx.x;
    const int lane = tid & 31;
    const int warp = tid >> 5;

    // --- recover separable 1D window: w1[j] = win[55+j] / sum_j win[55+j] ---
    float rowsum = 0.f;
#pragma unroll
    for (int j = 0; j < 11; j++) rowsum += __ldg(win + 55 + j);
    const float invr = 1.0f / rowsum;
    ull ww[11];
#pragma unroll
    for (int j = 0; j < 11; j++) {
        float w = __ldg(win + 55 + j) * invr;
        ww[j] = f2pack(w, w);
    }

    const int ox = blockIdx.x * TILE_W;
    const int oy = blockIdx.y * TILE_H;
    const int pz = blockIdx.z;                  // plane pair 0..23
    const float* p0 = pred + (size_t)pz * 524288;
    const float* p1 = p0 + 262144;
    const float* t0 = targ + (size_t)pz * 524288;
    const float* t1 = t0 + 262144;

    // --- load 32x42 halo tile (zero pad) into interleaved {p,t} cells ---
#pragma unroll
    for (int i = 0; i < 6; i++) {
        int idx = tid + i * 256;
        if (idx < IN_ROWS * IN_W) {
            int r = idx / IN_W, c = idx - r * IN_W;
            int gy = oy + r - HALO, gx = ox + c - HALO;
            bool inb = ((unsigned)gy < 512u) && ((unsigned)gx < 512u);
            float a0 = 0.f, a1 = 0.f, b0 = 0.f, b1 = 0.f;
            if (inb) {
                int g = gy * 512 + gx;
                a0 = __ldg(p0 + g); a1 = __ldg(p1 + g);
                b0 = __ldg(t0 + g); b1 = __ldg(t1 + g);
            }
            ull* cell = spt + r * SPT_RSTRIDE + 2 * c;
            *reinterpret_cast<ulonglong2*>(cell) =
                make_ulonglong2(f2pack(a0, a1), f2pack(b0, b1));
        }
    }
    __syncthreads();

    // --- horizontal blur: lane = row (32 exactly), warp = 4-wide x-group ---
    {
        const int r  = lane;
        const int x0 = warp * 4;
        const ull* rowp = spt + r * SPT_RSTRIDE + 2 * x0;
        ull am1[4], am2[4], asq[4], apt[4];
#pragma unroll
        for (int j = 0; j < 4; j++) { am1[j] = 0ULL; am2[j] = 0ULL; asq[j] = 0ULL; apt[j] = 0ULL; }
#pragma unroll
        for (int k = 0; k < 14; k++) {
            ulonglong2 PT = *reinterpret_cast<const ulonglong2*>(rowp + 2 * k);
            ull p = PT.x, t = PT.y;
            ull sq = f2fma(p, p, f2mul(t, t));   // p^2 + t^2
            ull pt = f2mul(p, t);
#pragma unroll
            for (int j = 0; j < 4; j++) {
                const int ki = k - j;
                if (ki >= 0 && ki <= 10) {
                    ull w = ww[ki];
                    am1[j] = f2fma(p,  w, am1[j]);
                    am2[j] = f2fma(t,  w, am2[j]);
                    asq[j] = f2fma(sq, w, asq[j]);
                    apt[j] = f2fma(pt, w, apt[j]);
                }
            }
        }
#pragma unroll
        for (int j = 0; j < 4; j++) {
            ull* c01 = hb01 + r * HB_RSTRIDE + 2 * (x0 + j);
            ull* c23 = hb23 + r * HB_RSTRIDE + 2 * (x0 + j);
            *reinterpret_cast<ulonglong2*>(c01) = make_ulonglong2(am1[j], am2[j]);
            *reinterpret_cast<ulonglong2*>(c23) = make_ulonglong2(asq[j], apt[j]);
        }
    }
    __syncthreads();

    // --- vertical blur + epilogue: all 8 warps; warps 0..5 -> 3 rows, 6..7 -> 2 ---
    float lsum;
    if (warp < 6) {
        const int y0 = warp * 3;
        lsum = v_phase<3>(hb01, hb23, ww, lane, y0, oy + y0);
    } else {
        const int y0 = 18 + (warp - 6) * 2;
        lsum = v_phase<2>(hb01, hb23, ww, lane, y0, oy + y0);
    }

    // --- block reduction -> double atomic + last-block finalize ---
#pragma unroll
    for (int o = 16; o; o >>= 1) lsum += __shfl_xor_sync(0xffffffffu, lsum, o);
    __shared__ float warp_part[8];
    if (lane == 0) warp_part[warp] = lsum;
    __syncthreads();
    if (tid == 0) {
        float v = 0.f;
#pragma unroll
        for (int i = 0; i < 8; i++) v += warp_part[i];
        atomicAdd(&g_acc, (double)v);
        __threadfence();
        unsigned int old = atomicAdd(&g_done, 1u);
        if (old == NBLOCKS - 1u) {
            __threadfence();
            double total = *((volatile double*)&g_acc);
            out[0] = 1.0f - (float)(total * (1.0 / NPIX));
            g_acc  = 0.0;
            g_done = 0u;
        }
    }
}

extern "C" void kernel_launch(void* const* d_in, const int* in_sizes, int n_in,
                              void* d_out, int out_size)
{
    const float* pred = (const float*)d_in[0];
    const float* targ = (const float*)d_in[1];
    const float* win  = (const float*)d_in[2];
    float* out = (float*)d_out;

    const int smem_bytes = 55808;
    cudaFuncSetAttribute(ssim_main_k, cudaFuncAttributeMaxDynamicSharedMemorySize, smem_bytes);

    dim3 grid(16, 24, 24), blk(256);
    ssim_main_k<<<grid, blk, smem_bytes>>>(pred, targ, win, out);
}

// round 8
// speedup vs baseline: 1.1806x; 1.0239x over previous
#include <cuda_runtime.h>
#include <cstdint>

typedef unsigned long long ull;

// ---------- packed f32x2 helpers ----------
__device__ __forceinline__ ull f2pack(float lo, float hi) {
    ull r; asm("mov.b64 %0,{%1,%2};" : "=l"(r) : "f"(lo), "f"(hi)); return r;
}
__device__ __forceinline__ void f2unpack(ull a, float& lo, float& hi) {
    asm("mov.b64 {%0,%1},%2;" : "=f"(lo), "=f"(hi) : "l"(a));
}
__device__ __forceinline__ ull f2mul(ull a, ull b) {
    ull r; asm("mul.rn.f32x2 %0,%1,%2;" : "=l"(r) : "l"(a), "l"(b)); return r;
}
__device__ __forceinline__ ull f2add(ull a, ull b) {
    ull r; asm("add.rn.f32x2 %0,%1,%2;" : "=l"(r) : "l"(a), "l"(b)); return r;
}
__device__ __forceinline__ ull f2fma(ull a, ull b, ull c) {
    ull r; asm("fma.rn.f32x2 %0,%1,%2,%3;" : "=l"(r) : "l"(a), "l"(b), "l"(c)); return r;
}

#define TW       64                 // tile width (pixel columns / pair cells)
#define TH       64                 // tile height (output rows)
#define IN_W     74                 // TW + 10
#define TOT_R    74                 // TH + 10 input rows per tile
#define CHUNK    16
#define NCH      5                  // chunks of 16,16,16,16,10
#define IN_PITCH 184                // ull per input row (16B cells, swizzled), even for LDS.128
#define HB_PITCH 67                 // ull per hb/stage row (8B cells, swizzled)
#define SIG_STRIDE (CHUNK * HB_PITCH)   // 1072 ull per signal plane
#define REG0_ULL 4288               // max(input 16*184=2944, stage 4*1072=4288)
#define HB_ULL   4288               // 4 * 1072
#define NPIX     12582912.0         // 48 * 512 * 512
#define NBLOCKS  1536               // 8 x 8 x 24

// swizzled offsets (conflict-free, verified per 8/16-lane phase)
__device__ __forceinline__ int in_off(int x) { return 2 * x + 2 * (x >> 2); }   // 16B cells
__device__ __forceinline__ int c_off(int c)  { return c + (c >> 4); }           // 8B cells

__device__ double        g_acc  = 0.0;
__device__ unsigned int  g_done = 0u;

// dynamic smem: rg0[4288] (input chunk / epilogue staging overlay) | hb[4288]
// total 8576 ull = 68608 B -> 3 CTAs/SM
__global__ __launch_bounds__(256, 3) void ssim_main_k(
    const float* __restrict__ pred,
    const float* __restrict__ targ,
    const float* __restrict__ win,
    float* __restrict__ out)
{
    extern __shared__ ull sm[];
    ull* rg0 = sm;                  // input chunk, later staging
    ull* hb  = sm + REG0_ULL;

    const int tid  = threadIdx.x;
    const int lane = tid & 31;
    const int warp = tid >> 5;

    // --- recover separable 1D window: w1[j] = win[55+j] / sum_j win[55+j] ---
    float rowsum = 0.f;
#pragma unroll
    for (int j = 0; j < 11; j++) rowsum += __ldg(win + 55 + j);
    const float invr = 1.0f / rowsum;
    ull ww[11];
#pragma unroll
    for (int j = 0; j < 11; j++) {
        float w = __ldg(win + 55 + j) * invr;
        ww[j] = f2pack(w, w);
    }

    const int ox = blockIdx.x * TW;
    const int oy = blockIdx.y * TH;
    const int pz = blockIdx.z;                  // plane pair 0..23
    const float* p0 = pred + (size_t)pz * 524288;
    const float* p1 = p0 + 262144;
    const float* t0 = targ + (size_t)pz * 524288;
    const float* t1 = t0 + 262144;

    // identities
    const int hr  = tid >> 4;          // h-phase row within chunk
    const int hx0 = (tid & 15) * 4;    // h-phase first output column
    const int vc  = tid & 63;          // v-phase column
    const int vs  = tid >> 6;          // v-phase signal (0:mu1 1:mu2 2:sq 3:pt)

    const ull TWO  = f2pack(2.0f, 2.0f);
    const ull C1p  = f2pack(1e-4f, 1e-4f);
    const ull C2p  = f2pack(9e-4f, 9e-4f);
    const ull C12p = f2pack(1e-4f + 9e-4f, 1e-4f + 9e-4f);
    const ull EPSp = f2pack(1e-8f, 1e-8f);
    const ull SGN  = 0x8000000080000000ULL;

    // v sliding shift-register accumulators (live across chunks)
    ull acc[11];
#pragma unroll
    for (int d = 0; d < 11; d++) acc[d] = 0ULL;

    float lsum = 0.f;

    for (int ch = 0; ch < NCH; ch++) {
        const int cs    = ch * CHUNK;
        const int nrows = (TOT_R - cs < CHUNK) ? (TOT_R - cs) : CHUNK;

        // ---- load input chunk (zero pad OOB), interleaved {p,t} 16B cells ----
        for (int idx = tid; idx < nrows * IN_W; idx += 256) {
            int r = idx / IN_W;
            int x = idx - r * IN_W;
            int gy = oy - 5 + cs + r;
            int gx = ox - 5 + x;
            float a0 = 0.f, a1 = 0.f, b0 = 0.f, b1 = 0.f;
            if (((unsigned)gy < 512u) && ((unsigned)gx < 512u)) {
                int g = gy * 512 + gx;
                a0 = __ldg(p0 + g); a1 = __ldg(p1 + g);
                b0 = __ldg(t0 + g); b1 = __ldg(t1 + g);
            }
            ull* cell = rg0 + r * IN_PITCH + in_off(x);
            cell[0] = f2pack(a0, a1);
            cell[1] = f2pack(b0, b1);
        }
        __syncthreads();

        // ---- horizontal blur: thread = (row, 4-output x-group) ----
        if (hr < nrows) {
            const ull* rp = rg0 + hr * IN_PITCH;
            ull am1[4], am2[4], asq[4], apt[4];
#pragma unroll
            for (int j = 0; j < 4; j++) { am1[j]=0ULL; am2[j]=0ULL; asq[j]=0ULL; apt[j]=0ULL; }
#pragma unroll
            for (int k = 0; k < 14; k++) {
                ulonglong2 PT = *reinterpret_cast<const ulonglong2*>(rp + in_off(hx0 + k));
                ull p = PT.x, t = PT.y;
                ull sq = f2fma(p, p, f2mul(t, t));
                ull pt = f2mul(p, t);
#pragma unroll
                for (int j = 0; j < 4; j++) {
                    const int ki = k - j;
                    if (ki >= 0 && ki <= 10) {
                        ull w = ww[ki];
                        am1[j] = f2fma(p,  w, am1[j]);
                        am2[j] = f2fma(t,  w, am2[j]);
                        asq[j] = f2fma(sq, w, asq[j]);
                        apt[j] = f2fma(pt, w, apt[j]);
                    }
                }
            }
#pragma unroll
            for (int j = 0; j < 4; j++) {
                int co = c_off(hx0 + j);
                hb[0 * SIG_STRIDE + hr * HB_PITCH + co] = am1[j];
                hb[1 * SIG_STRIDE + hr * HB_PITCH + co] = am2[j];
                hb[2 * SIG_STRIDE + hr * HB_PITCH + co] = asq[j];
                hb[3 * SIG_STRIDE + hr * HB_PITCH + co] = apt[j];
            }
        }
        __syncthreads();

        // ---- vertical consume: shift-register, emit completed rows to staging ----
        {
            const ull* hsig = hb  + vs * SIG_STRIDE + c_off(vc);
            ull*       ssig = rg0 + vs * SIG_STRIDE + c_off(vc);
#pragma unroll
            for (int r = 0; r < CHUNK; r++) {
                if (r < nrows) {
                    ull v = hsig[r * HB_PITCH];
#pragma unroll
                    for (int d = 10; d >= 1; d--) acc[d] = f2fma(v, ww[d], acc[d - 1]);
                    acc[0] = f2mul(v, ww[0]);
                    int ri = cs + r;
                    if (ri >= 10) {
                        int slot = (ri - 10) & 15;
                        ssig[slot * HB_PITCH] = acc[10];
                    }
                }
            }
        }
        __syncthreads();

        // ---- epilogue for rows emitted this chunk ----
        {
            int e0 = (cs >= 10) ? (cs - 10) : 0;
            int e1 = cs + nrows - 10;
            int ntask = (e1 - e0) * TW;
            for (int t = tid; t < ntask; t += 256) {
                int yl = e0 + (t >> 6);
                int c  = t & 63;
                int base = (yl & 15) * HB_PITCH + c_off(c);
                ull bm1 = rg0[0 * SIG_STRIDE + base];
                ull bm2 = rg0[1 * SIG_STRIDE + base];
                ull bsq = rg0[2 * SIG_STRIDE + base];
                ull bpt = rg0[3 * SIG_STRIDE + base];
                ull m12   = f2mul(bm1, bm2);
                ull den1  = f2fma(bm1, bm1, f2fma(bm2, bm2, C1p));   // mu1^2+mu2^2+C1
                ull den2  = f2add(f2add(bsq, C12p), den1 ^ SGN);     // bsq - den1 + C1+C2
                ull sig12 = f2add(bpt, m12 ^ SGN);                   // bpt - m12
                ull num1  = f2fma(m12,   TWO, C1p);
                ull num2  = f2fma(sig12, TWO, C2p);
                ull num   = f2mul(num1, num2);
                ull den   = f2fma(den1, den2, EPSp);
                float n0, n1, d0, d1;
                f2unpack(num, n0, n1);
                f2unpack(den, d0, d1);
                lsum += __fdividef(n0, d0) + __fdividef(n1, d1);
            }
        }
        __syncthreads();
    }

    // --- block reduction -> double atomic + last-block finalize ---
#pragma unroll
    for (int o = 16; o; o >>= 1) lsum += __shfl_xor_sync(0xffffffffu, lsum, o);
    __shared__ float warp_part[8];
    if (lane == 0) warp_part[warp] = lsum;
    __syncthreads();
    if (tid == 0) {
        float v = 0.f;
#pragma unroll
        for (int i = 0; i < 8; i++) v += warp_part[i];
        atomicAdd(&g_acc, (double)v);
        __threadfence();
        unsigned int old = atomicAdd(&g_done, 1u);
        if (old == NBLOCKS - 1u) {
            __threadfence();
            double total = *((volatile double*)&g_acc);
            out[0] = 1.0f - (float)(total * (1.0 / NPIX));
            g_acc  = 0.0;
            g_done = 0u;
        }
    }
}

extern "C" void kernel_launch(void* const* d_in, const int* in_sizes, int n_in,
                              void* d_out, int out_size)
{
    const float* pred = (const float*)d_in[0];
    const float* targ = (const float*)d_in[1];
    const float* win  = (const float*)d_in[2];
    float* out = (float*)d_out;

    const int smem_bytes = (REG0_ULL + HB_ULL) * 8;   // 68608
    cudaFuncSetAttribute(ssim_main_k, cudaFuncAttributeMaxDynamicSharedMemorySize, smem_bytes);

    dim3 grid(8, 8, 24), blk(256);
    ssim_main_k<<<grid, blk, smem_bytes>>>(pred, targ, win, out);
}